// round 13
// baseline (speedup 1.0000x reference)
#include <cuda_runtime.h>
#include <cstdint>

// DCN cross layer, L=3, D=1024, B=16384 — algebraic form, cp.async pipeline.
//   a_l = dot(x, W_l); d_ml = dot(bias_m, W_l); alpha recurrence;
//   out = alpha*x + (b0+b1+b2).
// R12 = R11 with 12 warps/CTA (384 thr, 1 CTA/SM) and a 2-stage ring:
// occupancy +50% for latency hiding; prefetch distance 1 iteration (~1000cyc)
// still covers DRAM (577). Warp-private 2x8KB ring filled by cp.async.cg;
// x regs stay live dot->output (no re-read); W smem loads shared across the
// pair; no CTA barriers in the row path. smem = 16KB + 12*2*8KB = 208KB.

static constexpr int D  = 1024;
static constexpr int F4 = D / 4;              // 256
static constexpr int THREADS = 384;
static constexpr int NWARP = 12;
static constexpr int GRID = 152;              // 1 CTA/SM
static constexpr int TOTALW = GRID * NWARP;   // 1824
static constexpr int STAGES = 2;
static constexpr int STAGE_FLOATS = 2 * D;    // 2 rows = 8KB
// dynamic smem layout (floats): Ws[3*1024] Bs[1024] rings[12*2*2048]
static constexpr int SMEM_W_OFF  = 0;                  // float4 units
static constexpr int SMEM_B_OFF  = 3 * F4;             // float4 units
static constexpr int SMEM_X_OFF  = (4 * F4) * 4;       // float units = 4096
static constexpr int SMEM_TOTAL  = (SMEM_X_OFF + NWARP * STAGES * STAGE_FLOATS) * 4;

__device__ __forceinline__ float dot4(float4 a, float4 b) {
    return fmaf(a.x, b.x, fmaf(a.y, b.y, fmaf(a.z, b.z, a.w * b.w)));
}
__device__ __forceinline__ float wred(float v) {
#pragma unroll
    for (int o = 16; o > 0; o >>= 1)
        v += __shfl_xor_sync(0xffffffffu, v, o);
    return v;
}
__device__ __forceinline__ uint32_t smem_u32(const void* p) {
    return (uint32_t)__cvta_generic_to_shared(p);
}
__device__ __forceinline__ void cp16(uint32_t dst, const void* src) {
    asm volatile("cp.async.cg.shared.global [%0], [%1], 16;" :: "r"(dst), "l"(src));
}
__device__ __forceinline__ void cp_commit() {
    asm volatile("cp.async.commit_group;" ::: "memory");
}
__device__ __forceinline__ void cp_wait1() {
    asm volatile("cp.async.wait_group 1;" ::: "memory");
}

__global__ __launch_bounds__(THREADS, 1)
void cross_layer_kernel(const float* __restrict__ x,
                        const float* __restrict__ W,
                        const float* __restrict__ bias,
                        float* __restrict__ out,
                        int total_pairs)
{
    extern __shared__ float4 smem4[];
    float4* Ws = smem4 + SMEM_W_OFF;          // [3][256] float4
    float4* Bs = smem4 + SMEM_B_OFF;          // [256] float4
    float*  Xs = reinterpret_cast<float*>(smem4) + SMEM_X_OFF;
    __shared__ float dred[NWARP][2];

    const int t    = threadIdx.x;
    const int warp = t >> 5;
    const int lane = t & 31;

    // ---- prologue (once per CTA): 384 threads, 1024 float4 slots -> strided ----
    const float4* W4 = reinterpret_cast<const float4*>(W);
    const float4* B4 = reinterpret_cast<const float4*>(bias);
    for (int i = t; i < 3 * F4; i += THREADS) Ws[i] = W4[i];
    for (int i = t; i < F4; i += THREADS) {
        float4 b0 = B4[i], b1 = B4[F4 + i], b2 = B4[2 * F4 + i];
        float4 bs;
        bs.x = b0.x + b1.x + b2.x;  bs.y = b0.y + b1.y + b2.y;
        bs.z = b0.z + b1.z + b2.z;  bs.w = b0.w + b1.w + b2.w;
        Bs[i] = bs;
    }
    // d-constants: each warp covers slots warp*? -> simpler: every warp computes
    // partials over a strided range, combine via dred.
    {
        float s01 = 0.f, s2 = 0.f;
        for (int i = t; i < F4; i += THREADS) {
            float4 b0 = B4[i], b1 = B4[F4 + i], b2 = B4[2 * F4 + i];
            float4 w1 = W4[F4 + i], w2 = W4[2 * F4 + i];
            s01 += dot4(b0, w1);
            s2  += dot4(b0, w2) + dot4(b1, w2);
        }
        s01 = wred(s01); s2 = wred(s2);
        if (lane == 0) { dred[warp][0] = s01; dred[warp][1] = s2; }
    }
    __syncthreads();
    float d01 = 0.f, d2 = 0.f;
#pragma unroll
    for (int w = 0; w < NWARP; w++) { d01 += dred[w][0]; d2 += dred[w][1]; }

    // ---- warp-private 2-stage async pipeline ----
    float* ring = Xs + warp * STAGES * STAGE_FLOATS;
    const uint32_t ring_u32 = smem_u32(ring);
    const int base = warp * GRID + blockIdx.x;     // same remainder on every SM

    auto issue = [&](int s, int p) {
        if (p < total_pairs) {
            const float* src = x + (size_t)p * STAGE_FLOATS;
            const uint32_t dst = ring_u32 + (uint32_t)s * STAGE_FLOATS * 4;
#pragma unroll
            for (int j = 0; j < 16; j++) {
                const int c = j * 32 + lane;           // 16B chunk index
                cp16(dst + c * 16, src + c * 4);
            }
        }
        cp_commit();
    };

    issue(0, base);

    int i = 0;
    for (int p = base; p < total_pairs; p += TOTALW, ++i) {
        // issue next stage first, then wait for current (distance = 1 iteration)
        issue((i + 1) & 1, p + TOTALW);
        cp_wait1();                        // <=1 pending -> current stage done
        __syncwarp();

        const float4* xs = reinterpret_cast<const float4*>(ring + (i & 1) * STAGE_FLOATS);

        // both rows smem -> regs (live through output)
        float4 xa[8], xb[8];
#pragma unroll
        for (int j = 0; j < 8; j++) xa[j] = xs[lane + 32 * j];
#pragma unroll
        for (int j = 0; j < 8; j++) xb[j] = xs[F4 + lane + 32 * j];

        // dots: each W smem load feeds both rows
        float a0 = 0.f, a1 = 0.f, a2 = 0.f;
        float c0 = 0.f, c1 = 0.f, c2 = 0.f;
#pragma unroll
        for (int j = 0; j < 8; j++) {
            const int idx = lane + 32 * j;
            float4 q0 = Ws[idx], q1 = Ws[F4 + idx], q2 = Ws[2 * F4 + idx];
            a0 = fmaf(xa[j].x, q0.x, fmaf(xa[j].y, q0.y, fmaf(xa[j].z, q0.z, fmaf(xa[j].w, q0.w, a0))));
            c0 = fmaf(xb[j].x, q0.x, fmaf(xb[j].y, q0.y, fmaf(xb[j].z, q0.z, fmaf(xb[j].w, q0.w, c0))));
            a1 = fmaf(xa[j].x, q1.x, fmaf(xa[j].y, q1.y, fmaf(xa[j].z, q1.z, fmaf(xa[j].w, q1.w, a1))));
            c1 = fmaf(xb[j].x, q1.x, fmaf(xb[j].y, q1.y, fmaf(xb[j].z, q1.z, fmaf(xb[j].w, q1.w, c1))));
            a2 = fmaf(xa[j].x, q2.x, fmaf(xa[j].y, q2.y, fmaf(xa[j].z, q2.z, fmaf(xa[j].w, q2.w, a2))));
            c2 = fmaf(xb[j].x, q2.x, fmaf(xb[j].y, q2.y, fmaf(xb[j].z, q2.z, fmaf(xb[j].w, q2.w, c2))));
        }

        a0 = wred(a0); a1 = wred(a1); a2 = wred(a2);
        c0 = wred(c0); c1 = wred(c1); c2 = wred(c2);

        float ala = 1.f + a0;
        ala += fmaf(ala, a1, d01);
        ala += fmaf(ala, a2, d2);
        float alb = 1.f + c0;
        alb += fmaf(alb, c1, d01);
        alb += fmaf(alb, c2, d2);

        // output straight from live registers
        float4* orp = reinterpret_cast<float4*>(out) + (size_t)p * 2 * F4;
#pragma unroll
        for (int j = 0; j < 8; j++) {
            const int idx = lane + 32 * j;
            float4 c = Bs[idx];
            float4 oa, ob;
            oa.x = fmaf(ala, xa[j].x, c.x);  ob.x = fmaf(alb, xb[j].x, c.x);
            oa.y = fmaf(ala, xa[j].y, c.y);  ob.y = fmaf(alb, xb[j].y, c.y);
            oa.z = fmaf(ala, xa[j].z, c.z);  ob.z = fmaf(alb, xb[j].z, c.z);
            oa.w = fmaf(ala, xa[j].w, c.w);  ob.w = fmaf(alb, xb[j].w, c.w);
            __stcs(orp + idx, oa);
            __stcs(orp + F4 + idx, ob);
        }
    }
}

extern "C" void kernel_launch(void* const* d_in, const int* in_sizes, int n_in,
                              void* d_out, int out_size)
{
    const float* x    = (const float*)d_in[0];   // (B, D, 1)
    const float* W    = (const float*)d_in[1];   // (L, D, 1)
    const float* bias = (const float*)d_in[2];   // (L, D, 1)
    float* out = (float*)d_out;

    const int B = in_sizes[0] / D;               // 16384

    cudaFuncSetAttribute(cross_layer_kernel,
                         cudaFuncAttributeMaxDynamicSharedMemorySize, SMEM_TOTAL);
    cross_layer_kernel<<<GRID, THREADS, SMEM_TOTAL>>>(x, W, bias, out, B / 2);
}

// round 14
// speedup vs baseline: 1.0015x; 1.0015x over previous
#include <cuda_runtime.h>
#include <cstdint>

// DCN cross layer, L=3, D=1024, B=16384 — algebraic form, cp.async pipeline.
//   a_l = dot(x, W_l); d_ml = dot(bias_m, W_l); alpha recurrence;
//   out = alpha*x + (b0+b1+b2).
// R12 = R11 with 12 warps/CTA (384 thr, 1 CTA/SM) and a 2-stage ring:
// occupancy +50% for latency hiding; prefetch distance 1 iteration (~1000cyc)
// still covers DRAM (577). Warp-private 2x8KB ring filled by cp.async.cg;
// x regs stay live dot->output (no re-read); W smem loads shared across the
// pair; no CTA barriers in the row path. smem = 16KB + 12*2*8KB = 208KB.

static constexpr int D  = 1024;
static constexpr int F4 = D / 4;              // 256
static constexpr int THREADS = 384;
static constexpr int NWARP = 12;
static constexpr int GRID = 152;              // 1 CTA/SM
static constexpr int TOTALW = GRID * NWARP;   // 1824
static constexpr int STAGES = 2;
static constexpr int STAGE_FLOATS = 2 * D;    // 2 rows = 8KB
// dynamic smem layout (floats): Ws[3*1024] Bs[1024] rings[12*2*2048]
static constexpr int SMEM_W_OFF  = 0;                  // float4 units
static constexpr int SMEM_B_OFF  = 3 * F4;             // float4 units
static constexpr int SMEM_X_OFF  = (4 * F4) * 4;       // float units = 4096
static constexpr int SMEM_TOTAL  = (SMEM_X_OFF + NWARP * STAGES * STAGE_FLOATS) * 4;

__device__ __forceinline__ float dot4(float4 a, float4 b) {
    return fmaf(a.x, b.x, fmaf(a.y, b.y, fmaf(a.z, b.z, a.w * b.w)));
}
__device__ __forceinline__ float wred(float v) {
#pragma unroll
    for (int o = 16; o > 0; o >>= 1)
        v += __shfl_xor_sync(0xffffffffu, v, o);
    return v;
}
__device__ __forceinline__ uint32_t smem_u32(const void* p) {
    return (uint32_t)__cvta_generic_to_shared(p);
}
__device__ __forceinline__ void cp16(uint32_t dst, const void* src) {
    asm volatile("cp.async.cg.shared.global [%0], [%1], 16;" :: "r"(dst), "l"(src));
}
__device__ __forceinline__ void cp_commit() {
    asm volatile("cp.async.commit_group;" ::: "memory");
}
__device__ __forceinline__ void cp_wait1() {
    asm volatile("cp.async.wait_group 1;" ::: "memory");
}

__global__ __launch_bounds__(THREADS, 1)
void cross_layer_kernel(const float* __restrict__ x,
                        const float* __restrict__ W,
                        const float* __restrict__ bias,
                        float* __restrict__ out,
                        int total_pairs)
{
    extern __shared__ float4 smem4[];
    float4* Ws = smem4 + SMEM_W_OFF;          // [3][256] float4
    float4* Bs = smem4 + SMEM_B_OFF;          // [256] float4
    float*  Xs = reinterpret_cast<float*>(smem4) + SMEM_X_OFF;
    __shared__ float dred[NWARP][2];

    const int t    = threadIdx.x;
    const int warp = t >> 5;
    const int lane = t & 31;

    // ---- prologue (once per CTA): 384 threads, 1024 float4 slots -> strided ----
    const float4* W4 = reinterpret_cast<const float4*>(W);
    const float4* B4 = reinterpret_cast<const float4*>(bias);
    for (int i = t; i < 3 * F4; i += THREADS) Ws[i] = W4[i];
    for (int i = t; i < F4; i += THREADS) {
        float4 b0 = B4[i], b1 = B4[F4 + i], b2 = B4[2 * F4 + i];
        float4 bs;
        bs.x = b0.x + b1.x + b2.x;  bs.y = b0.y + b1.y + b2.y;
        bs.z = b0.z + b1.z + b2.z;  bs.w = b0.w + b1.w + b2.w;
        Bs[i] = bs;
    }
    // d-constants: each warp covers slots warp*? -> simpler: every warp computes
    // partials over a strided range, combine via dred.
    {
        float s01 = 0.f, s2 = 0.f;
        for (int i = t; i < F4; i += THREADS) {
            float4 b0 = B4[i], b1 = B4[F4 + i], b2 = B4[2 * F4 + i];
            float4 w1 = W4[F4 + i], w2 = W4[2 * F4 + i];
            s01 += dot4(b0, w1);
            s2  += dot4(b0, w2) + dot4(b1, w2);
        }
        s01 = wred(s01); s2 = wred(s2);
        if (lane == 0) { dred[warp][0] = s01; dred[warp][1] = s2; }
    }
    __syncthreads();
    float d01 = 0.f, d2 = 0.f;
#pragma unroll
    for (int w = 0; w < NWARP; w++) { d01 += dred[w][0]; d2 += dred[w][1]; }

    // ---- warp-private 2-stage async pipeline ----
    float* ring = Xs + warp * STAGES * STAGE_FLOATS;
    const uint32_t ring_u32 = smem_u32(ring);
    const int base = warp * GRID + blockIdx.x;     // same remainder on every SM

    auto issue = [&](int s, int p) {
        if (p < total_pairs) {
            const float* src = x + (size_t)p * STAGE_FLOATS;
            const uint32_t dst = ring_u32 + (uint32_t)s * STAGE_FLOATS * 4;
#pragma unroll
            for (int j = 0; j < 16; j++) {
                const int c = j * 32 + lane;           // 16B chunk index
                cp16(dst + c * 16, src + c * 4);
            }
        }
        cp_commit();
    };

    issue(0, base);

    int i = 0;
    for (int p = base; p < total_pairs; p += TOTALW, ++i) {
        // issue next stage first, then wait for current (distance = 1 iteration)
        issue((i + 1) & 1, p + TOTALW);
        cp_wait1();                        // <=1 pending -> current stage done
        __syncwarp();

        const float4* xs = reinterpret_cast<const float4*>(ring + (i & 1) * STAGE_FLOATS);

        // both rows smem -> regs (live through output)
        float4 xa[8], xb[8];
#pragma unroll
        for (int j = 0; j < 8; j++) xa[j] = xs[lane + 32 * j];
#pragma unroll
        for (int j = 0; j < 8; j++) xb[j] = xs[F4 + lane + 32 * j];

        // dots: each W smem load feeds both rows
        float a0 = 0.f, a1 = 0.f, a2 = 0.f;
        float c0 = 0.f, c1 = 0.f, c2 = 0.f;
#pragma unroll
        for (int j = 0; j < 8; j++) {
            const int idx = lane + 32 * j;
            float4 q0 = Ws[idx], q1 = Ws[F4 + idx], q2 = Ws[2 * F4 + idx];
            a0 = fmaf(xa[j].x, q0.x, fmaf(xa[j].y, q0.y, fmaf(xa[j].z, q0.z, fmaf(xa[j].w, q0.w, a0))));
            c0 = fmaf(xb[j].x, q0.x, fmaf(xb[j].y, q0.y, fmaf(xb[j].z, q0.z, fmaf(xb[j].w, q0.w, c0))));
            a1 = fmaf(xa[j].x, q1.x, fmaf(xa[j].y, q1.y, fmaf(xa[j].z, q1.z, fmaf(xa[j].w, q1.w, a1))));
            c1 = fmaf(xb[j].x, q1.x, fmaf(xb[j].y, q1.y, fmaf(xb[j].z, q1.z, fmaf(xb[j].w, q1.w, c1))));
            a2 = fmaf(xa[j].x, q2.x, fmaf(xa[j].y, q2.y, fmaf(xa[j].z, q2.z, fmaf(xa[j].w, q2.w, a2))));
            c2 = fmaf(xb[j].x, q2.x, fmaf(xb[j].y, q2.y, fmaf(xb[j].z, q2.z, fmaf(xb[j].w, q2.w, c2))));
        }

        a0 = wred(a0); a1 = wred(a1); a2 = wred(a2);
        c0 = wred(c0); c1 = wred(c1); c2 = wred(c2);

        float ala = 1.f + a0;
        ala += fmaf(ala, a1, d01);
        ala += fmaf(ala, a2, d2);
        float alb = 1.f + c0;
        alb += fmaf(alb, c1, d01);
        alb += fmaf(alb, c2, d2);

        // output straight from live registers
        float4* orp = reinterpret_cast<float4*>(out) + (size_t)p * 2 * F4;
#pragma unroll
        for (int j = 0; j < 8; j++) {
            const int idx = lane + 32 * j;
            float4 c = Bs[idx];
            float4 oa, ob;
            oa.x = fmaf(ala, xa[j].x, c.x);  ob.x = fmaf(alb, xb[j].x, c.x);
            oa.y = fmaf(ala, xa[j].y, c.y);  ob.y = fmaf(alb, xb[j].y, c.y);
            oa.z = fmaf(ala, xa[j].z, c.z);  ob.z = fmaf(alb, xb[j].z, c.z);
            oa.w = fmaf(ala, xa[j].w, c.w);  ob.w = fmaf(alb, xb[j].w, c.w);
            __stcs(orp + idx, oa);
            __stcs(orp + F4 + idx, ob);
        }
    }
}

extern "C" void kernel_launch(void* const* d_in, const int* in_sizes, int n_in,
                              void* d_out, int out_size)
{
    const float* x    = (const float*)d_in[0];   // (B, D, 1)
    const float* W    = (const float*)d_in[1];   // (L, D, 1)
    const float* bias = (const float*)d_in[2];   // (L, D, 1)
    float* out = (float*)d_out;

    const int B = in_sizes[0] / D;               // 16384

    cudaFuncSetAttribute(cross_layer_kernel,
                         cudaFuncAttributeMaxDynamicSharedMemorySize, SMEM_TOTAL);
    cross_layer_kernel<<<GRID, THREADS, SMEM_TOTAL>>>(x, W, bias, out, B / 2);
}

// round 15
// speedup vs baseline: 1.0518x; 1.0503x over previous
#include <cuda_runtime.h>
#include <cstdint>

// DCN cross layer, L=3, D=1024, B=16384 — algebraic form, cp.async pipeline.
//   a_l = dot(x, W_l); d_ml = dot(bias_m, W_l); alpha recurrence;
//   out = alpha*x + (b0+b1+b2).
// R12 = R11 with 12 warps/CTA (384 thr, 1 CTA/SM) and a 2-stage ring:
// occupancy +50% for latency hiding; prefetch distance 1 iteration (~1000cyc)
// still covers DRAM (577). Warp-private 2x8KB ring filled by cp.async.cg;
// x regs stay live dot->output (no re-read); W smem loads shared across the
// pair; no CTA barriers in the row path. smem = 16KB + 12*2*8KB = 208KB.

static constexpr int D  = 1024;
static constexpr int F4 = D / 4;              // 256
static constexpr int THREADS = 384;
static constexpr int NWARP = 12;
static constexpr int GRID = 152;              // 1 CTA/SM
static constexpr int TOTALW = GRID * NWARP;   // 1824
static constexpr int STAGES = 2;
static constexpr int STAGE_FLOATS = 2 * D;    // 2 rows = 8KB
// dynamic smem layout (floats): Ws[3*1024] Bs[1024] rings[12*2*2048]
static constexpr int SMEM_W_OFF  = 0;                  // float4 units
static constexpr int SMEM_B_OFF  = 3 * F4;             // float4 units
static constexpr int SMEM_X_OFF  = (4 * F4) * 4;       // float units = 4096
static constexpr int SMEM_TOTAL  = (SMEM_X_OFF + NWARP * STAGES * STAGE_FLOATS) * 4;

__device__ __forceinline__ float dot4(float4 a, float4 b) {
    return fmaf(a.x, b.x, fmaf(a.y, b.y, fmaf(a.z, b.z, a.w * b.w)));
}
__device__ __forceinline__ float wred(float v) {
#pragma unroll
    for (int o = 16; o > 0; o >>= 1)
        v += __shfl_xor_sync(0xffffffffu, v, o);
    return v;
}
__device__ __forceinline__ uint32_t smem_u32(const void* p) {
    return (uint32_t)__cvta_generic_to_shared(p);
}
__device__ __forceinline__ void cp16(uint32_t dst, const void* src) {
    asm volatile("cp.async.cg.shared.global [%0], [%1], 16;" :: "r"(dst), "l"(src));
}
__device__ __forceinline__ void cp_commit() {
    asm volatile("cp.async.commit_group;" ::: "memory");
}
__device__ __forceinline__ void cp_wait1() {
    asm volatile("cp.async.wait_group 1;" ::: "memory");
}

__global__ __launch_bounds__(THREADS, 1)
void cross_layer_kernel(const float* __restrict__ x,
                        const float* __restrict__ W,
                        const float* __restrict__ bias,
                        float* __restrict__ out,
                        int total_pairs)
{
    extern __shared__ float4 smem4[];
    float4* Ws = smem4 + SMEM_W_OFF;          // [3][256] float4
    float4* Bs = smem4 + SMEM_B_OFF;          // [256] float4
    float*  Xs = reinterpret_cast<float*>(smem4) + SMEM_X_OFF;
    __shared__ float dred[NWARP][2];

    const int t    = threadIdx.x;
    const int warp = t >> 5;
    const int lane = t & 31;

    // ---- prologue (once per CTA): 384 threads, 1024 float4 slots -> strided ----
    const float4* W4 = reinterpret_cast<const float4*>(W);
    const float4* B4 = reinterpret_cast<const float4*>(bias);
    for (int i = t; i < 3 * F4; i += THREADS) Ws[i] = W4[i];
    for (int i = t; i < F4; i += THREADS) {
        float4 b0 = B4[i], b1 = B4[F4 + i], b2 = B4[2 * F4 + i];
        float4 bs;
        bs.x = b0.x + b1.x + b2.x;  bs.y = b0.y + b1.y + b2.y;
        bs.z = b0.z + b1.z + b2.z;  bs.w = b0.w + b1.w + b2.w;
        Bs[i] = bs;
    }
    // d-constants: each warp covers slots warp*? -> simpler: every warp computes
    // partials over a strided range, combine via dred.
    {
        float s01 = 0.f, s2 = 0.f;
        for (int i = t; i < F4; i += THREADS) {
            float4 b0 = B4[i], b1 = B4[F4 + i], b2 = B4[2 * F4 + i];
            float4 w1 = W4[F4 + i], w2 = W4[2 * F4 + i];
            s01 += dot4(b0, w1);
            s2  += dot4(b0, w2) + dot4(b1, w2);
        }
        s01 = wred(s01); s2 = wred(s2);
        if (lane == 0) { dred[warp][0] = s01; dred[warp][1] = s2; }
    }
    __syncthreads();
    float d01 = 0.f, d2 = 0.f;
#pragma unroll
    for (int w = 0; w < NWARP; w++) { d01 += dred[w][0]; d2 += dred[w][1]; }

    // ---- warp-private 2-stage async pipeline ----
    float* ring = Xs + warp * STAGES * STAGE_FLOATS;
    const uint32_t ring_u32 = smem_u32(ring);
    const int base = warp * GRID + blockIdx.x;     // same remainder on every SM

    auto issue = [&](int s, int p) {
        if (p < total_pairs) {
            const float* src = x + (size_t)p * STAGE_FLOATS;
            const uint32_t dst = ring_u32 + (uint32_t)s * STAGE_FLOATS * 4;
#pragma unroll
            for (int j = 0; j < 16; j++) {
                const int c = j * 32 + lane;           // 16B chunk index
                cp16(dst + c * 16, src + c * 4);
            }
        }
        cp_commit();
    };

    issue(0, base);

    int i = 0;
    for (int p = base; p < total_pairs; p += TOTALW, ++i) {
        // issue next stage first, then wait for current (distance = 1 iteration)
        issue((i + 1) & 1, p + TOTALW);
        cp_wait1();                        // <=1 pending -> current stage done
        __syncwarp();

        const float4* xs = reinterpret_cast<const float4*>(ring + (i & 1) * STAGE_FLOATS);

        // both rows smem -> regs (live through output)
        float4 xa[8], xb[8];
#pragma unroll
        for (int j = 0; j < 8; j++) xa[j] = xs[lane + 32 * j];
#pragma unroll
        for (int j = 0; j < 8; j++) xb[j] = xs[F4 + lane + 32 * j];

        // dots: each W smem load feeds both rows
        float a0 = 0.f, a1 = 0.f, a2 = 0.f;
        float c0 = 0.f, c1 = 0.f, c2 = 0.f;
#pragma unroll
        for (int j = 0; j < 8; j++) {
            const int idx = lane + 32 * j;
            float4 q0 = Ws[idx], q1 = Ws[F4 + idx], q2 = Ws[2 * F4 + idx];
            a0 = fmaf(xa[j].x, q0.x, fmaf(xa[j].y, q0.y, fmaf(xa[j].z, q0.z, fmaf(xa[j].w, q0.w, a0))));
            c0 = fmaf(xb[j].x, q0.x, fmaf(xb[j].y, q0.y, fmaf(xb[j].z, q0.z, fmaf(xb[j].w, q0.w, c0))));
            a1 = fmaf(xa[j].x, q1.x, fmaf(xa[j].y, q1.y, fmaf(xa[j].z, q1.z, fmaf(xa[j].w, q1.w, a1))));
            c1 = fmaf(xb[j].x, q1.x, fmaf(xb[j].y, q1.y, fmaf(xb[j].z, q1.z, fmaf(xb[j].w, q1.w, c1))));
            a2 = fmaf(xa[j].x, q2.x, fmaf(xa[j].y, q2.y, fmaf(xa[j].z, q2.z, fmaf(xa[j].w, q2.w, a2))));
            c2 = fmaf(xb[j].x, q2.x, fmaf(xb[j].y, q2.y, fmaf(xb[j].z, q2.z, fmaf(xb[j].w, q2.w, c2))));
        }

        a0 = wred(a0); a1 = wred(a1); a2 = wred(a2);
        c0 = wred(c0); c1 = wred(c1); c2 = wred(c2);

        float ala = 1.f + a0;
        ala += fmaf(ala, a1, d01);
        ala += fmaf(ala, a2, d2);
        float alb = 1.f + c0;
        alb += fmaf(alb, c1, d01);
        alb += fmaf(alb, c2, d2);

        // output straight from live registers
        float4* orp = reinterpret_cast<float4*>(out) + (size_t)p * 2 * F4;
#pragma unroll
        for (int j = 0; j < 8; j++) {
            const int idx = lane + 32 * j;
            float4 c = Bs[idx];
            float4 oa, ob;
            oa.x = fmaf(ala, xa[j].x, c.x);  ob.x = fmaf(alb, xb[j].x, c.x);
            oa.y = fmaf(ala, xa[j].y, c.y);  ob.y = fmaf(alb, xb[j].y, c.y);
            oa.z = fmaf(ala, xa[j].z, c.z);  ob.z = fmaf(alb, xb[j].z, c.z);
            oa.w = fmaf(ala, xa[j].w, c.w);  ob.w = fmaf(alb, xb[j].w, c.w);
            __stcs(orp + idx, oa);
            __stcs(orp + F4 + idx, ob);
        }
    }
}

extern "C" void kernel_launch(void* const* d_in, const int* in_sizes, int n_in,
                              void* d_out, int out_size)
{
    const float* x    = (const float*)d_in[0];   // (B, D, 1)
    const float* W    = (const float*)d_in[1];   // (L, D, 1)
    const float* bias = (const float*)d_in[2];   // (L, D, 1)
    float* out = (float*)d_out;

    const int B = in_sizes[0] / D;               // 16384

    cudaFuncSetAttribute(cross_layer_kernel,
                         cudaFuncAttributeMaxDynamicSharedMemorySize, SMEM_TOTAL);
    cross_layer_kernel<<<GRID, THREADS, SMEM_TOTAL>>>(x, W, bias, out, B / 2);
}